// round 15
// baseline (speedup 1.0000x reference)
#include <cuda_runtime.h>
#include <cuda_fp16.h>
#include <cuda_bf16.h>
#include <math.h>
#include <stdint.h>

#define BB 8
#define NN 2048
#define DD 32
#define XRBS 16                     // rows per xy row-block
#define XNRB (NN / XRBS)            // 128
#define RBS 16                      // rows per sym row-block
#define NRB (NN / RBS)              // 128

#define BPAD 33                     // build smem row stride (33 ≡ 1 mod 32: conflict-free)
#define SMEM_BUILD ((4 * 128 * BPAD + 256) * (int)sizeof(float))   // ~68.6KB

// ---------------- scratch (device globals; no allocations) ----------------
__device__ __nv_bfloat16 g_Exy[(size_t)BB * NN * NN]; // exp((sh_l - dist(x_l,y_k))/2), bf16
__device__ __half g_Exx[(size_t)BB * NN * NN];        // exp(-dist/2), fp16 (upper tiles valid)
__device__ __half g_Eyy[(size_t)BB * NN * NN];
__device__ float g_shift[BB * NN];
__device__ float g_pot[4][BB * NN];              // 0:f 1:g 2:fx 3:fy
__device__ float g_wg[BB * NN];                  // b * exp(g)
__device__ float g_wap[2][BB * NN];              // a * exp(f - sh/2), parity buffered
__device__ float g_wsym[2][2][BB * NN];          // [parity][0:xx,1:yy]
__device__ float g_colpart[XNRB][BB][NN];        // xy column partial sums
__device__ float g_colpartS[2][NRB][BB][NN];     // sym column partials per slot
__device__ float g_symrow[2][BB * NN];           // sym row sums (cols >= start part)
__device__ float g_c[4][BB * NN];                // eval contributions

// ---------------- small helpers ----------------
__device__ __forceinline__ uint32_t f2tf32(float f) {
    uint32_t r;
    asm("cvt.rna.tf32.f32 %0, %1;" : "=r"(r) : "f"(f));
    return r;
}
__device__ __forceinline__ void mma_tf32(float d[4],
    uint32_t a0, uint32_t a1, uint32_t a2, uint32_t a3, uint32_t b0, uint32_t b1)
{
    asm("mma.sync.aligned.m16n8k8.row.col.f32.tf32.tf32.f32 "
        "{%0,%1,%2,%3}, {%4,%5,%6,%7}, {%8,%9}, {%0,%1,%2,%3};"
        : "+f"(d[0]), "+f"(d[1]), "+f"(d[2]), "+f"(d[3])
        : "r"(a0), "r"(a1), "r"(a2), "r"(a3), "r"(b0), "r"(b1));
}

// ---------------- row shifts ----------------
__global__ void shift_kernel(const float* __restrict__ x, const float* __restrict__ y)
{
    const int b = blockIdx.y;
    const int l = blockIdx.x * 128 + threadIdx.x;
    const float* Pb = x + (size_t)b * NN * DD;
    const float* Qb = y + (size_t)b * NN * DD;

    __shared__ float sq[128][DD + 1];
    for (int i = threadIdx.x; i < 128 * DD; i += 128)
        sq[i >> 5][i & 31] = Qb[i];
    __syncthreads();

    float p[DD];
    #pragma unroll
    for (int d = 0; d < DD; d++) p[d] = Pb[(size_t)l * DD + d];

    float mn = 3.4e38f;
    for (int k = 0; k < 128; k++) {
        float acc = 0.f;
        #pragma unroll
        for (int d = 0; d < DD; d++) {
            float df = p[d] - sq[k][d];
            acc = fmaf(df, df, acc);
        }
        mn = fminf(mn, acc);
    }
    g_shift[b * NN + l] = mn;
}

// ---------------- init ----------------
__global__ void init_kernel(const float* __restrict__ a, const float* __restrict__ bm)
{
    int i = blockIdx.x * 256 + threadIdx.x;
    if (i < BB * NN) {
        g_pot[0][i] = 0.f; g_pot[1][i] = 0.f;
        g_pot[2][i] = 0.f; g_pot[3][i] = 0.f;
        g_wg[i] = bm[i];
        g_wap[0][i] = a[i] * __expf(-0.5f * g_shift[i]);
        g_wsym[0][0][i] = a[i];
        g_wsym[0][1][i] = bm[i];
    }
}

// ---------------- tensor-core build core ----------------
// block 256 (8 warps), 128x128 tile. tf32 hi/lo split STAGED IN SMEM once per tile
// (removes ~8x redundant per-warp CVT work). Dynamic smem, 3 blocks/SM.
// OUT: 0 -> g_Exy (bf16, row-shifted); 1 -> g_Exx (fp16); 2 -> g_Eyy (fp16)
template <int USE_SHIFT, int OUT>
__device__ __forceinline__ void build_core(const float* __restrict__ P,
                                           const float* __restrict__ Q,
                                           int b, int l0, int k0)
{
    extern __shared__ float dsm[];
    float (*sp)[BPAD]  = (float(*)[BPAD])(dsm);                    // hi (tf32 bits as float)
    float (*sq)[BPAD]  = (float(*)[BPAD])(dsm + 128 * BPAD);
    float (*spl)[BPAD] = (float(*)[BPAD])(dsm + 2 * 128 * BPAD);   // lo
    float (*sql)[BPAD] = (float(*)[BPAD])(dsm + 3 * 128 * BPAD);
    float* snp = dsm + 4 * 128 * BPAD;
    float* snq = snp + 128;

    const int tid = threadIdx.x;
    const float* Pb = P + (size_t)b * NN * DD;
    const float* Qb = Q + (size_t)b * NN * DD;

    for (int i = tid; i < 128 * DD; i += 256) {
        int r = i >> 5, d = i & 31;
        sp[r][d] = Pb[(size_t)(l0 + r) * DD + d];
        sq[r][d] = Qb[(size_t)(k0 + r) * DD + d];
    }
    __syncthreads();

    if (tid < 128) {
        float s = 0.f;
        #pragma unroll
        for (int d = 0; d < DD; d++) s = fmaf(sp[tid][d], sp[tid][d], s);
        snp[tid] = s;
    } else {
        int r = tid - 128;
        float s = 0.f;
        #pragma unroll
        for (int d = 0; d < DD; d++) s = fmaf(sq[r][d], sq[r][d], s);
        snq[r] = s;
    }
    __syncthreads();

    // split stage: hi in place, lo to companion arrays (each element once)
    for (int i = tid; i < 128 * DD; i += 256) {
        int r = i >> 5, d = i & 31;
        float vp = sp[r][d];
        uint32_t hp = f2tf32(vp);
        sp[r][d]  = __uint_as_float(hp);
        spl[r][d] = __uint_as_float(f2tf32(vp - __uint_as_float(hp)));
        float vq = sq[r][d];
        uint32_t hq = f2tf32(vq);
        sq[r][d]  = __uint_as_float(hq);
        sql[r][d] = __uint_as_float(f2tf32(vq - __uint_as_float(hq)));
    }
    __syncthreads();

    const int warp = tid >> 5, lane = tid & 31;
    const int g = lane >> 2, tg = lane & 3;
    const int nb = warp * 16;

    float acc[8][2][4];
    #pragma unroll
    for (int r = 0; r < 8; r++)
        #pragma unroll
        for (int c = 0; c < 2; c++)
            #pragma unroll
            for (int q = 0; q < 4; q++) acc[r][c][q] = 0.f;

    #pragma unroll
    for (int kt = 0; kt < 4; kt++) {
        const int kc = kt * 8;
        uint32_t bh[2][2], bl[2][2];
        #pragma unroll
        for (int c = 0; c < 2; c++) {
            bh[c][0] = __float_as_uint(sq[nb + c * 8 + g][kc + tg]);
            bh[c][1] = __float_as_uint(sq[nb + c * 8 + g][kc + tg + 4]);
            bl[c][0] = __float_as_uint(sql[nb + c * 8 + g][kc + tg]);
            bl[c][1] = __float_as_uint(sql[nb + c * 8 + g][kc + tg + 4]);
        }
        #pragma unroll
        for (int r = 0; r < 8; r++) {
            uint32_t h0 = __float_as_uint(sp[r * 16 + g][kc + tg]);
            uint32_t h1 = __float_as_uint(sp[r * 16 + g + 8][kc + tg]);
            uint32_t h2 = __float_as_uint(sp[r * 16 + g][kc + tg + 4]);
            uint32_t h3 = __float_as_uint(sp[r * 16 + g + 8][kc + tg + 4]);
            uint32_t l0r = __float_as_uint(spl[r * 16 + g][kc + tg]);
            uint32_t l1r = __float_as_uint(spl[r * 16 + g + 8][kc + tg]);
            uint32_t l2r = __float_as_uint(spl[r * 16 + g][kc + tg + 4]);
            uint32_t l3r = __float_as_uint(spl[r * 16 + g + 8][kc + tg + 4]);
            #pragma unroll
            for (int c = 0; c < 2; c++) {
                mma_tf32(acc[r][c], h0, h1, h2, h3, bh[c][0], bh[c][1]);
                mma_tf32(acc[r][c], h0, h1, h2, h3, bl[c][0], bl[c][1]);
                mma_tf32(acc[r][c], l0r, l1r, l2r, l3r, bh[c][0], bh[c][1]);
            }
        }
    }

    const size_t base = (size_t)b * NN * NN;
    #pragma unroll
    for (int r = 0; r < 8; r++) {
        const int row0 = l0 + r * 16 + g;
        const int row1 = row0 + 8;
        const float nx0 = snp[r * 16 + g], nx1 = snp[r * 16 + g + 8];
        const float sh0 = USE_SHIFT ? g_shift[b * NN + row0] : 0.f;
        const float sh1 = USE_SHIFT ? g_shift[b * NN + row1] : 0.f;
        #pragma unroll
        for (int c = 0; c < 2; c++) {
            const int col = k0 + nb + c * 8 + tg * 2;
            const float ny0 = snq[nb + c * 8 + tg * 2];
            const float ny1 = snq[nb + c * 8 + tg * 2 + 1];
            float e00 = __expf(0.5f * (sh0 - fmaxf(nx0 + ny0 - 2.f * acc[r][c][0], 0.f)));
            float e01 = __expf(0.5f * (sh0 - fmaxf(nx0 + ny1 - 2.f * acc[r][c][1], 0.f)));
            float e10 = __expf(0.5f * (sh1 - fmaxf(nx1 + ny0 - 2.f * acc[r][c][2], 0.f)));
            float e11 = __expf(0.5f * (sh1 - fmaxf(nx1 + ny1 - 2.f * acc[r][c][3], 0.f)));
            if (OUT == 0) {
                *(__nv_bfloat162*)&g_Exy[base + (size_t)row0 * NN + col] =
                    __floats2bfloat162_rn(e00, e01);
                *(__nv_bfloat162*)&g_Exy[base + (size_t)row1 * NN + col] =
                    __floats2bfloat162_rn(e10, e11);
            } else {
                __half* M = (OUT == 1) ? g_Exx : g_Eyy;
                *(__half2*)&M[base + (size_t)row0 * NN + col] = __floats2half2_rn(e00, e01);
                *(__half2*)&M[base + (size_t)row1 * NN + col] = __floats2half2_rn(e10, e11);
            }
        }
    }
}

__global__ void __launch_bounds__(256, 3) build_xy(const float* __restrict__ x,
                                                   const float* __restrict__ y)
{ build_core<1, 0>(x, y, blockIdx.z, blockIdx.y * 128, blockIdx.x * 128); }

// Merged sym builds: grid z = slot*BB + b. Upper-staircase tiles only.
__global__ void __launch_bounds__(256, 3) build_sym(const float* __restrict__ x,
                                                    const float* __restrict__ y)
{
    if (blockIdx.x < blockIdx.y) return;
    const int slot = blockIdx.z / BB;
    const int b = blockIdx.z % BB;
    if (slot == 0) build_core<0, 1>(x, x, b, blockIdx.y * 128, blockIdx.x * 128);
    else           build_core<0, 2>(y, y, b, blockIdx.y * 128, blockIdx.x * 128);
}

// ---------------- row-batch compute helpers (8 rows) ----------------
__device__ __forceinline__ void rows8_bf16(const uint4 m[8], const float* swap8,
                                           const float4& wg0, const float4& wg1,
                                           float rd[8], float colacc[8])
{
    #pragma unroll
    for (int rr = 0; rr < 8; rr++) {
        float2 e0 = __bfloat1622float2(*reinterpret_cast<const __nv_bfloat162*>(&m[rr].x));
        float2 e1 = __bfloat1622float2(*reinterpret_cast<const __nv_bfloat162*>(&m[rr].y));
        float2 e2 = __bfloat1622float2(*reinterpret_cast<const __nv_bfloat162*>(&m[rr].z));
        float2 e3 = __bfloat1622float2(*reinterpret_cast<const __nv_bfloat162*>(&m[rr].w));
        float wr = swap8[rr];
        float s = 0.f;
        s = fmaf(e0.x, wg0.x, s); s = fmaf(e0.y, wg0.y, s);
        s = fmaf(e1.x, wg0.z, s); s = fmaf(e1.y, wg0.w, s);
        s = fmaf(e2.x, wg1.x, s); s = fmaf(e2.y, wg1.y, s);
        s = fmaf(e3.x, wg1.z, s); s = fmaf(e3.y, wg1.w, s);
        rd[rr] = s;
        colacc[0] = fmaf(e0.x, wr, colacc[0]); colacc[1] = fmaf(e0.y, wr, colacc[1]);
        colacc[2] = fmaf(e1.x, wr, colacc[2]); colacc[3] = fmaf(e1.y, wr, colacc[3]);
        colacc[4] = fmaf(e2.x, wr, colacc[4]); colacc[5] = fmaf(e2.y, wr, colacc[5]);
        colacc[6] = fmaf(e3.x, wr, colacc[6]); colacc[7] = fmaf(e3.y, wr, colacc[7]);
    }
}

__device__ __forceinline__ void rows8_fp16(const uint4 m[8], const float* swap8,
                                           const float4& wg0, const float4& wg1,
                                           float rd[8], float colacc[8])
{
    #pragma unroll
    for (int rr = 0; rr < 8; rr++) {
        float2 e0 = __half22float2(*reinterpret_cast<const __half2*>(&m[rr].x));
        float2 e1 = __half22float2(*reinterpret_cast<const __half2*>(&m[rr].y));
        float2 e2 = __half22float2(*reinterpret_cast<const __half2*>(&m[rr].z));
        float2 e3 = __half22float2(*reinterpret_cast<const __half2*>(&m[rr].w));
        float wr = swap8[rr];
        float s = 0.f;
        s = fmaf(e0.x, wg0.x, s); s = fmaf(e0.y, wg0.y, s);
        s = fmaf(e1.x, wg0.z, s); s = fmaf(e1.y, wg0.w, s);
        s = fmaf(e2.x, wg1.x, s); s = fmaf(e2.y, wg1.y, s);
        s = fmaf(e3.x, wg1.z, s); s = fmaf(e3.y, wg1.w, s);
        rd[rr] = s;
        colacc[0] = fmaf(e0.x, wr, colacc[0]); colacc[1] = fmaf(e0.y, wr, colacc[1]);
        colacc[2] = fmaf(e1.x, wr, colacc[2]); colacc[3] = fmaf(e1.y, wr, colacc[3]);
        colacc[4] = fmaf(e2.x, wr, colacc[4]); colacc[5] = fmaf(e2.y, wr, colacc[5]);
        colacc[6] = fmaf(e3.x, wr, colacc[6]); colacc[7] = fmaf(e3.y, wr, colacc[7]);
    }
}

// ---------------- xy main pass: row sums + column partials, 8-deep MLP ----------------
// grid (XNRB=128, BB), block 256 = 8 warps; warp w covers cols [w*256, w*256+256)
__global__ void __launch_bounds__(256) xy_main(const float* __restrict__ a, int par, int mode)
{
    const int b = blockIdx.y, rb = blockIdx.x;
    const int tid = threadIdx.x, warp = tid >> 5, lane = tid & 31;
    const int c0 = warp * 256 + lane * 8;

    __shared__ float swap_s[XRBS];
    __shared__ float rowpart[XRBS][9];

    if (tid < XRBS) swap_s[tid] = g_wap[par][b * NN + rb * XRBS + tid];

    const float4 wg0 = *(const float4*)&g_wg[b * NN + c0];
    const float4 wg1 = *(const float4*)&g_wg[b * NN + c0 + 4];
    __syncthreads();

    const __nv_bfloat16* Srow = g_Exy + ((size_t)b * NN + rb * XRBS) * NN + c0;

    float colacc[8];
    #pragma unroll
    for (int j = 0; j < 8; j++) colacc[j] = 0.f;

    #pragma unroll
    for (int g8 = 0; g8 < XRBS / 8; g8++) {
        uint4 m[8];
        #pragma unroll
        for (int rr = 0; rr < 8; rr++)
            m[rr] = __ldg((const uint4*)(Srow + (size_t)(g8 * 8 + rr) * NN));

        float rd[8];
        rows8_bf16(m, &swap_s[g8 * 8], wg0, wg1, rd, colacc);

        #pragma unroll
        for (int o = 16; o; o >>= 1) {
            #pragma unroll
            for (int rr = 0; rr < 8; rr++)
                rd[rr] += __shfl_xor_sync(0xffffffffu, rd[rr], o);
        }
        if (lane == 0) {
            #pragma unroll
            for (int rr = 0; rr < 8; rr++) rowpart[g8 * 8 + rr][warp] = rd[rr];
        }
    }

    float* cp = &g_colpart[rb][b][c0];
    *(float4*)cp       = make_float4(colacc[0], colacc[1], colacc[2], colacc[3]);
    *(float4*)(cp + 4) = make_float4(colacc[4], colacc[5], colacc[6], colacc[7]);

    __syncthreads();

    if (tid < XRBS) {
        const int row = rb * XRBS + tid;
        const int idx = b * NN + row;
        float tot = 0.f;
        #pragma unroll
        for (int w = 0; w < 8; w++) tot += rowpart[tid][w];
        const float sh = g_shift[idx];
        if (mode == 0) {
            float fn = 0.5f * (g_pot[0][idx] - logf(tot) + 0.5f * sh);
            g_pot[0][idx] = fn;
            g_wap[par ^ 1][idx] = a[idx] * __expf(fn - 0.5f * sh);
        } else {
            g_c[0][idx] = a[idx] * (0.5f * sh - logf(tot));
        }
    }
}

// ---------------- xy finalize ----------------
__global__ void xy_fin(const float* __restrict__ bm, int mode)
{
    const int i = blockIdx.x * 256 + threadIdx.x;       // i = b*NN + k
    const int b = i >> 11, k = i & (NN - 1);
    float T = 0.f;
    #pragma unroll 8
    for (int rb = 0; rb < XNRB; rb++) T += g_colpart[rb][b][k];
    if (mode == 0) {
        float gn = 0.5f * (g_pot[1][i] - logf(T));
        g_pot[1][i] = gn;
        g_wg[i] = bm[i] * __expf(gn);
    } else {
        g_c[1][i] = -bm[i] * logf(T);
    }
}

// ---------------- sym main pass (SYMV, upper triangle) ----------------
// grid (NRB/2, BB, 2). Block bx handles row-blocks {bx, NRB-1-bx}, cols >= 16*i each.
// wact (warp-uniform) gates compute+shuffles; lact (per-lane) only predicates load/store.
__global__ void __launch_bounds__(256) sym_main(int par)
{
    const int slot = blockIdx.z, b = blockIdx.y, bx = blockIdx.x;
    const int tid = threadIdx.x, warp = tid >> 5, lane = tid & 31;
    const int c0 = warp * 256 + lane * 8;
    const __half* M = slot ? g_Eyy : g_Exx;
    const float* wv = g_wsym[par][slot] + b * NN;

    __shared__ float swap_s[RBS];
    __shared__ float rowpart[RBS][9];

    const float4 w0 = *(const float4*)&wv[c0];
    const float4 w1 = *(const float4*)&wv[c0 + 4];

    #pragma unroll
    for (int s = 0; s < 2; s++) {
        const int i = s ? (NRB - 1 - bx) : bx;
        const int start = i * RBS;
        const bool wact = (warp * 256 + 256) > start;   // warp-uniform
        const bool lact = c0 >= start;                  // per-lane

        __syncthreads();
        if (tid < RBS) swap_s[tid] = wv[start + tid];
        __syncthreads();

        if (wact) {
            const __half* Srow = M + ((size_t)b * NN + start) * NN + c0;
            float colacc[8];
            #pragma unroll
            for (int j = 0; j < 8; j++) colacc[j] = 0.f;

            #pragma unroll
            for (int g8 = 0; g8 < RBS / 8; g8++) {
                uint4 m[8];
                #pragma unroll
                for (int rr = 0; rr < 8; rr++)
                    m[rr] = lact ? __ldg((const uint4*)(Srow + (size_t)(g8 * 8 + rr) * NN))
                                 : make_uint4(0u, 0u, 0u, 0u);

                float rd[8];
                rows8_fp16(m, &swap_s[g8 * 8], w0, w1, rd, colacc);

                #pragma unroll
                for (int o = 16; o; o >>= 1) {
                    #pragma unroll
                    for (int rr = 0; rr < 8; rr++)
                        rd[rr] += __shfl_xor_sync(0xffffffffu, rd[rr], o);
                }
                if (lane == 0) {
                    #pragma unroll
                    for (int rr = 0; rr < 8; rr++) rowpart[g8 * 8 + rr][warp] = rd[rr];
                }
            }

            if (lact) {
                float* cp = &g_colpartS[slot][i][b][c0];
                *(float4*)cp       = make_float4(colacc[0], colacc[1], colacc[2], colacc[3]);
                *(float4*)(cp + 4) = make_float4(colacc[4], colacc[5], colacc[6], colacc[7]);
            }
        } else if (lane == 0) {
            #pragma unroll
            for (int r = 0; r < RBS; r++) rowpart[r][warp] = 0.f;
        }

        __syncthreads();
        if (tid < RBS) {
            float tot = 0.f;
            #pragma unroll
            for (int w = 0; w < 8; w++) tot += rowpart[tid][w];
            g_symrow[slot][b * NN + start + tid] = tot;
        }
    }
}

// ---------------- sym finalize: S[r] = rowsum(r) + sum_{j<blk(r)} colpartS[j][r] ----------------
__global__ void sym_fin(const float* __restrict__ a, const float* __restrict__ bm,
                        int par, int mode)
{
    const int slot = blockIdx.y;
    const int i = blockIdx.x * 256 + threadIdx.x;       // i = b*NN + r
    const int b = i >> 11, r = i & (NN - 1);
    const int blk = r >> 4;                             // RBS = 16

    const float* cp = &g_colpartS[slot][0][b][r];
    const size_t stride = (size_t)BB * NN;
    float T0 = 0.f, T1 = 0.f, T2 = 0.f, T3 = 0.f;
    int j = 0;
    for (; j + 4 <= blk; j += 4) {
        T0 += cp[(size_t)j * stride];
        T1 += cp[(size_t)(j + 1) * stride];
        T2 += cp[(size_t)(j + 2) * stride];
        T3 += cp[(size_t)(j + 3) * stride];
    }
    for (; j < blk; j++) T0 += cp[(size_t)j * stride];
    float T = g_symrow[slot][i] + ((T0 + T1) + (T2 + T3));

    const float* meas = slot ? bm : a;
    if (mode == 0) {
        float pn = 0.5f * (g_pot[2 + slot][i] - logf(T));
        g_pot[2 + slot][i] = pn;
        g_wsym[par ^ 1][slot][i] = meas[i] * __expf(pn);
    } else {
        g_c[2 + slot][i] = -meas[i] * logf(T);
    }
}

// ---------------- final scalar ----------------
__global__ void final_reduce(float* __restrict__ out)
{
    const int tid = threadIdx.x;
    float s = 0.f;
    for (int i = tid; i < BB * NN; i += 1024)
        s += (g_c[0][i] + g_c[1][i]) - (g_c[2][i] + g_c[3][i]);
    #pragma unroll
    for (int o = 16; o; o >>= 1) s += __shfl_xor_sync(0xffffffffu, s, o);
    __shared__ float sm[32];
    if ((tid & 31) == 0) sm[tid >> 5] = s;
    __syncthreads();
    if (tid < 32) {
        float v = sm[tid];
        #pragma unroll
        for (int o = 16; o; o >>= 1) v += __shfl_xor_sync(0xffffffffu, v, o);
        if (tid == 0) out[0] = v / (float)BB;
    }
}

// ---------------- launcher: separate phase loops (L2 residency per phase) ----------------
extern "C" void kernel_launch(void* const* d_in, const int* in_sizes, int n_in,
                              void* d_out, int out_size)
{
    const float* x  = (const float*)d_in[0];
    const float* a  = (const float*)d_in[1];
    const float* y  = (const float*)d_in[2];
    const float* bm = (const float*)d_in[3];
    float* out = (float*)d_out;

    // allow >48KB dynamic smem on the builds (host attr set; idempotent, graph-safe)
    cudaFuncSetAttribute(build_xy,  cudaFuncAttributeMaxDynamicSharedMemorySize, SMEM_BUILD);
    cudaFuncSetAttribute(build_sym, cudaFuncAttributeMaxDynamicSharedMemorySize, SMEM_BUILD);

    shift_kernel<<<dim3(16, BB), 128>>>(x, y);
    init_kernel<<<(BB * NN + 255) / 256, 256>>>(a, bm);

    dim3 bg(16, 16, BB);         // xy build: 128x128 tiles
    dim3 bgs(16, 16, BB * 2);    // merged sym builds (z = slot*BB + b)
    dim3 xg(XNRB, BB);
    dim3 smg(NRB / 2, BB, 2);
    dim3 sfg(BB * NN / 256, 2);

    // ---- xy phase ----
    build_xy<<<bg, 256, SMEM_BUILD>>>(x, y);
    for (int it = 0; it < 10; it++) {
        xy_main<<<xg, 256>>>(a, it & 1, 0);
        xy_fin<<<BB * NN / 256, 256>>>(bm, 0);
    }
    xy_main<<<xg, 256>>>(a, 0, 1);           // c0 + final colparts (wap parity 0)
    xy_fin<<<BB * NN / 256, 256>>>(bm, 1);   // c1

    // ---- merged symmetric phases (upper triangles only) ----
    build_sym<<<bgs, 256, SMEM_BUILD>>>(x, y);
    for (int it = 0; it < 10; it++) {
        sym_main<<<smg, 256>>>(it & 1);
        sym_fin<<<sfg, 256>>>(a, bm, it & 1, 0);
    }
    sym_main<<<smg, 256>>>(0);               // final weights at parity 0
    sym_fin<<<sfg, 256>>>(a, bm, 0, 1);      // c2, c3

    final_reduce<<<1, 1024>>>(out);
}

// round 16
// speedup vs baseline: 1.0619x; 1.0619x over previous
#include <cuda_runtime.h>
#include <cuda_fp16.h>
#include <cuda_bf16.h>
#include <math.h>
#include <stdint.h>

#define BB 8
#define NN 2048
#define DD 32
#define XRBS 16                     // rows per xy row-block
#define XNRB (NN / XRBS)            // 128
#define RBS 16                      // rows per sym row-block
#define NRB (NN / RBS)              // 128

// ---------------- scratch (device globals; no allocations) ----------------
__device__ __nv_bfloat16 g_Exy[(size_t)BB * NN * NN]; // exp((sh_l - dist(x_l,y_k))/2), bf16
__device__ __half g_Exx[(size_t)BB * NN * NN];        // exp(-dist/2), fp16 (upper tiles valid)
__device__ __half g_Eyy[(size_t)BB * NN * NN];
__device__ float g_shift[BB * NN];
__device__ float g_pot[4][BB * NN];              // 0:f 1:g 2:fx 3:fy
__device__ float g_wg[BB * NN];                  // b * exp(g)
__device__ float g_wap[2][BB * NN];              // a * exp(f - sh/2), parity buffered
__device__ float g_wsym[2][2][BB * NN];          // [parity][0:xx,1:yy]
__device__ float g_colpart[XNRB][BB][NN];        // xy column partial sums
__device__ float g_colpartS[2][NRB][BB][NN];     // sym column partials per slot
__device__ float g_symrow[2][BB * NN];           // sym row sums (cols >= start part)
__device__ float g_c[4][BB * NN];                // eval contributions

// ---------------- small helpers ----------------
__device__ __forceinline__ uint32_t f2tf32(float f) {
    uint32_t r;
    asm("cvt.rna.tf32.f32 %0, %1;" : "=r"(r) : "f"(f));
    return r;
}
__device__ __forceinline__ void mma_tf32(float d[4],
    uint32_t a0, uint32_t a1, uint32_t a2, uint32_t a3, uint32_t b0, uint32_t b1)
{
    asm("mma.sync.aligned.m16n8k8.row.col.f32.tf32.tf32.f32 "
        "{%0,%1,%2,%3}, {%4,%5,%6,%7}, {%8,%9}, {%0,%1,%2,%3};"
        : "+f"(d[0]), "+f"(d[1]), "+f"(d[2]), "+f"(d[3])
        : "r"(a0), "r"(a1), "r"(a2), "r"(a3), "r"(b0), "r"(b1));
}

// ---------------- row shifts ----------------
__global__ void shift_kernel(const float* __restrict__ x, const float* __restrict__ y)
{
    const int b = blockIdx.y;
    const int l = blockIdx.x * 128 + threadIdx.x;
    const float* Pb = x + (size_t)b * NN * DD;
    const float* Qb = y + (size_t)b * NN * DD;

    __shared__ float sq[128][DD + 1];
    for (int i = threadIdx.x; i < 128 * DD; i += 128)
        sq[i >> 5][i & 31] = Qb[i];
    __syncthreads();

    float p[DD];
    #pragma unroll
    for (int d = 0; d < DD; d++) p[d] = Pb[(size_t)l * DD + d];

    float mn = 3.4e38f;
    for (int k = 0; k < 128; k++) {
        float acc = 0.f;
        #pragma unroll
        for (int d = 0; d < DD; d++) {
            float df = p[d] - sq[k][d];
            acc = fmaf(df, df, acc);
        }
        mn = fminf(mn, acc);
    }
    g_shift[b * NN + l] = mn;
}

// ---------------- init ----------------
__global__ void init_kernel(const float* __restrict__ a, const float* __restrict__ bm)
{
    int i = blockIdx.x * 256 + threadIdx.x;
    if (i < BB * NN) {
        g_pot[0][i] = 0.f; g_pot[1][i] = 0.f;
        g_pot[2][i] = 0.f; g_pot[3][i] = 0.f;
        g_wg[i] = bm[i];
        g_wap[0][i] = a[i] * __expf(-0.5f * g_shift[i]);
        g_wsym[0][0][i] = a[i];
        g_wsym[0][1][i] = bm[i];
    }
}

// ---------------- tensor-core build core (tf32 3-product split) ----------------
// block 256 (8 warps), tile 128x128 per batch, lb(256,3). (R13 form — fastest measured.)
template <int USE_SHIFT, int OUT>
__device__ __forceinline__ void build_core(const float* __restrict__ P,
                                           const float* __restrict__ Q)
{
    __shared__ float sp[128][DD + 4];
    __shared__ float sq[128][DD + 4];
    __shared__ float snp[128], snq[128];

    const int b  = blockIdx.z;
    const int l0 = blockIdx.y * 128;
    const int k0 = blockIdx.x * 128;
    const int tid = threadIdx.x;
    const float* Pb = P + (size_t)b * NN * DD;
    const float* Qb = Q + (size_t)b * NN * DD;

    for (int i = tid; i < 128 * DD; i += 256) {
        int r = i >> 5, d = i & 31;
        sp[r][d] = Pb[(size_t)(l0 + r) * DD + d];
        sq[r][d] = Qb[(size_t)(k0 + r) * DD + d];
    }
    __syncthreads();

    if (tid < 128) {
        float s = 0.f;
        #pragma unroll
        for (int d = 0; d < DD; d++) s = fmaf(sp[tid][d], sp[tid][d], s);
        snp[tid] = s;
    } else {
        int r = tid - 128;
        float s = 0.f;
        #pragma unroll
        for (int d = 0; d < DD; d++) s = fmaf(sq[r][d], sq[r][d], s);
        snq[r] = s;
    }
    __syncthreads();

    const int warp = tid >> 5, lane = tid & 31;
    const int g = lane >> 2, tg = lane & 3;
    const int nb = warp * 16;

    float acc[8][2][4];
    #pragma unroll
    for (int r = 0; r < 8; r++)
        #pragma unroll
        for (int c = 0; c < 2; c++)
            #pragma unroll
            for (int q = 0; q < 4; q++) acc[r][c][q] = 0.f;

    #pragma unroll
    for (int kt = 0; kt < 4; kt++) {
        const int kc = kt * 8;
        uint32_t bh[2][2], bl[2][2];
        #pragma unroll
        for (int c = 0; c < 2; c++) {
            float f0 = sq[nb + c * 8 + g][kc + tg];
            float f1 = sq[nb + c * 8 + g][kc + tg + 4];
            bh[c][0] = f2tf32(f0); bl[c][0] = f2tf32(f0 - __uint_as_float(bh[c][0]));
            bh[c][1] = f2tf32(f1); bl[c][1] = f2tf32(f1 - __uint_as_float(bh[c][1]));
        }
        #pragma unroll
        for (int r = 0; r < 8; r++) {
            float a00 = sp[r * 16 + g][kc + tg];
            float a10 = sp[r * 16 + g + 8][kc + tg];
            float a01 = sp[r * 16 + g][kc + tg + 4];
            float a11 = sp[r * 16 + g + 8][kc + tg + 4];
            uint32_t h0 = f2tf32(a00), h1 = f2tf32(a10), h2 = f2tf32(a01), h3 = f2tf32(a11);
            uint32_t l0r = f2tf32(a00 - __uint_as_float(h0));
            uint32_t l1r = f2tf32(a10 - __uint_as_float(h1));
            uint32_t l2r = f2tf32(a01 - __uint_as_float(h2));
            uint32_t l3r = f2tf32(a11 - __uint_as_float(h3));
            #pragma unroll
            for (int c = 0; c < 2; c++) {
                mma_tf32(acc[r][c], h0, h1, h2, h3, bh[c][0], bh[c][1]);
                mma_tf32(acc[r][c], h0, h1, h2, h3, bl[c][0], bl[c][1]);
                mma_tf32(acc[r][c], l0r, l1r, l2r, l3r, bh[c][0], bh[c][1]);
            }
        }
    }

    const size_t base = (size_t)b * NN * NN;
    #pragma unroll
    for (int r = 0; r < 8; r++) {
        const int row0 = l0 + r * 16 + g;
        const int row1 = row0 + 8;
        const float nx0 = snp[r * 16 + g], nx1 = snp[r * 16 + g + 8];
        const float sh0 = USE_SHIFT ? g_shift[b * NN + row0] : 0.f;
        const float sh1 = USE_SHIFT ? g_shift[b * NN + row1] : 0.f;
        #pragma unroll
        for (int c = 0; c < 2; c++) {
            const int col = k0 + nb + c * 8 + tg * 2;
            const float ny0 = snq[nb + c * 8 + tg * 2];
            const float ny1 = snq[nb + c * 8 + tg * 2 + 1];
            float e00 = __expf(0.5f * (sh0 - fmaxf(nx0 + ny0 - 2.f * acc[r][c][0], 0.f)));
            float e01 = __expf(0.5f * (sh0 - fmaxf(nx0 + ny1 - 2.f * acc[r][c][1], 0.f)));
            float e10 = __expf(0.5f * (sh1 - fmaxf(nx1 + ny0 - 2.f * acc[r][c][2], 0.f)));
            float e11 = __expf(0.5f * (sh1 - fmaxf(nx1 + ny1 - 2.f * acc[r][c][3], 0.f)));
            if (OUT == 0) {
                *(__nv_bfloat162*)&g_Exy[base + (size_t)row0 * NN + col] =
                    __floats2bfloat162_rn(e00, e01);
                *(__nv_bfloat162*)&g_Exy[base + (size_t)row1 * NN + col] =
                    __floats2bfloat162_rn(e10, e11);
            } else {
                __half* M = (OUT == 1) ? g_Exx : g_Eyy;
                *(__half2*)&M[base + (size_t)row0 * NN + col] = __floats2half2_rn(e00, e01);
                *(__half2*)&M[base + (size_t)row1 * NN + col] = __floats2half2_rn(e10, e11);
            }
        }
    }
}

__global__ void __launch_bounds__(256, 3) build_xy(const float* __restrict__ x,
                                                   const float* __restrict__ y)
{ build_core<1, 0>(x, y); }
// Sym builds: only upper-staircase 128-tiles needed (cols >= row-block start)
__global__ void __launch_bounds__(256, 3) build_xx(const float* __restrict__ x)
{ if (blockIdx.x < blockIdx.y) return; build_core<0, 1>(x, x); }
__global__ void __launch_bounds__(256, 3) build_yy(const float* __restrict__ y)
{ if (blockIdx.x < blockIdx.y) return; build_core<0, 2>(y, y); }

// ---------------- row-batch compute helpers (8 rows) ----------------
__device__ __forceinline__ void rows8_bf16(const uint4 m[8], const float* swap8,
                                           const float4& wg0, const float4& wg1,
                                           float rd[8], float colacc[8])
{
    #pragma unroll
    for (int rr = 0; rr < 8; rr++) {
        float2 e0 = __bfloat1622float2(*reinterpret_cast<const __nv_bfloat162*>(&m[rr].x));
        float2 e1 = __bfloat1622float2(*reinterpret_cast<const __nv_bfloat162*>(&m[rr].y));
        float2 e2 = __bfloat1622float2(*reinterpret_cast<const __nv_bfloat162*>(&m[rr].z));
        float2 e3 = __bfloat1622float2(*reinterpret_cast<const __nv_bfloat162*>(&m[rr].w));
        float wr = swap8[rr];
        float s = 0.f;
        s = fmaf(e0.x, wg0.x, s); s = fmaf(e0.y, wg0.y, s);
        s = fmaf(e1.x, wg0.z, s); s = fmaf(e1.y, wg0.w, s);
        s = fmaf(e2.x, wg1.x, s); s = fmaf(e2.y, wg1.y, s);
        s = fmaf(e3.x, wg1.z, s); s = fmaf(e3.y, wg1.w, s);
        rd[rr] = s;
        colacc[0] = fmaf(e0.x, wr, colacc[0]); colacc[1] = fmaf(e0.y, wr, colacc[1]);
        colacc[2] = fmaf(e1.x, wr, colacc[2]); colacc[3] = fmaf(e1.y, wr, colacc[3]);
        colacc[4] = fmaf(e2.x, wr, colacc[4]); colacc[5] = fmaf(e2.y, wr, colacc[5]);
        colacc[6] = fmaf(e3.x, wr, colacc[6]); colacc[7] = fmaf(e3.y, wr, colacc[7]);
    }
}

__device__ __forceinline__ void rows8_fp16(const uint4 m[8], const float* swap8,
                                           const float4& wg0, const float4& wg1,
                                           float rd[8], float colacc[8])
{
    #pragma unroll
    for (int rr = 0; rr < 8; rr++) {
        float2 e0 = __half22float2(*reinterpret_cast<const __half2*>(&m[rr].x));
        float2 e1 = __half22float2(*reinterpret_cast<const __half2*>(&m[rr].y));
        float2 e2 = __half22float2(*reinterpret_cast<const __half2*>(&m[rr].z));
        float2 e3 = __half22float2(*reinterpret_cast<const __half2*>(&m[rr].w));
        float wr = swap8[rr];
        float s = 0.f;
        s = fmaf(e0.x, wg0.x, s); s = fmaf(e0.y, wg0.y, s);
        s = fmaf(e1.x, wg0.z, s); s = fmaf(e1.y, wg0.w, s);
        s = fmaf(e2.x, wg1.x, s); s = fmaf(e2.y, wg1.y, s);
        s = fmaf(e3.x, wg1.z, s); s = fmaf(e3.y, wg1.w, s);
        rd[rr] = s;
        colacc[0] = fmaf(e0.x, wr, colacc[0]); colacc[1] = fmaf(e0.y, wr, colacc[1]);
        colacc[2] = fmaf(e1.x, wr, colacc[2]); colacc[3] = fmaf(e1.y, wr, colacc[3]);
        colacc[4] = fmaf(e2.x, wr, colacc[4]); colacc[5] = fmaf(e2.y, wr, colacc[5]);
        colacc[6] = fmaf(e3.x, wr, colacc[6]); colacc[7] = fmaf(e3.y, wr, colacc[7]);
    }
}

// ---------------- xy main pass: row sums + column partials, 8-deep MLP ----------------
// grid (XNRB=128, BB), block 256 = 8 warps; lb(256,5) -> 5 blocks/SM (reg-cap 51)
__global__ void __launch_bounds__(256, 5) xy_main(const float* __restrict__ a, int par, int mode)
{
    const int b = blockIdx.y, rb = blockIdx.x;
    const int tid = threadIdx.x, warp = tid >> 5, lane = tid & 31;
    const int c0 = warp * 256 + lane * 8;

    __shared__ float swap_s[XRBS];
    __shared__ float rowpart[XRBS][9];

    if (tid < XRBS) swap_s[tid] = g_wap[par][b * NN + rb * XRBS + tid];

    const float4 wg0 = *(const float4*)&g_wg[b * NN + c0];
    const float4 wg1 = *(const float4*)&g_wg[b * NN + c0 + 4];
    __syncthreads();

    const __nv_bfloat16* Srow = g_Exy + ((size_t)b * NN + rb * XRBS) * NN + c0;

    float colacc[8];
    #pragma unroll
    for (int j = 0; j < 8; j++) colacc[j] = 0.f;

    #pragma unroll
    for (int g8 = 0; g8 < XRBS / 8; g8++) {
        uint4 m[8];
        #pragma unroll
        for (int rr = 0; rr < 8; rr++)
            m[rr] = __ldg((const uint4*)(Srow + (size_t)(g8 * 8 + rr) * NN));

        float rd[8];
        rows8_bf16(m, &swap_s[g8 * 8], wg0, wg1, rd, colacc);

        #pragma unroll
        for (int o = 16; o; o >>= 1) {
            #pragma unroll
            for (int rr = 0; rr < 8; rr++)
                rd[rr] += __shfl_xor_sync(0xffffffffu, rd[rr], o);
        }
        if (lane == 0) {
            #pragma unroll
            for (int rr = 0; rr < 8; rr++) rowpart[g8 * 8 + rr][warp] = rd[rr];
        }
    }

    float* cp = &g_colpart[rb][b][c0];
    *(float4*)cp       = make_float4(colacc[0], colacc[1], colacc[2], colacc[3]);
    *(float4*)(cp + 4) = make_float4(colacc[4], colacc[5], colacc[6], colacc[7]);

    __syncthreads();

    if (tid < XRBS) {
        const int row = rb * XRBS + tid;
        const int idx = b * NN + row;
        float tot = 0.f;
        #pragma unroll
        for (int w = 0; w < 8; w++) tot += rowpart[tid][w];
        const float sh = g_shift[idx];
        if (mode == 0) {
            float fn = 0.5f * (g_pot[0][idx] - logf(tot) + 0.5f * sh);
            g_pot[0][idx] = fn;
            g_wap[par ^ 1][idx] = a[idx] * __expf(fn - 0.5f * sh);
        } else {
            g_c[0][idx] = a[idx] * (0.5f * sh - logf(tot));
        }
    }
}

// ---------------- xy finalize ----------------
__global__ void xy_fin(const float* __restrict__ bm, int mode)
{
    const int i = blockIdx.x * 256 + threadIdx.x;       // i = b*NN + k
    const int b = i >> 11, k = i & (NN - 1);
    float T = 0.f;
    #pragma unroll 8
    for (int rb = 0; rb < XNRB; rb++) T += g_colpart[rb][b][k];
    if (mode == 0) {
        float gn = 0.5f * (g_pot[1][i] - logf(T));
        g_pot[1][i] = gn;
        g_wg[i] = bm[i] * __expf(gn);
    } else {
        g_c[1][i] = -bm[i] * logf(T);
    }
}

// ---------------- sym main pass (SYMV, upper triangle) ----------------
// grid (NRB/2, BB, 2). Block bx handles row-blocks {bx, NRB-1-bx}, cols >= 16*i each.
__global__ void __launch_bounds__(256, 5) sym_main(int par)
{
    const int slot = blockIdx.z, b = blockIdx.y, bx = blockIdx.x;
    const int tid = threadIdx.x, warp = tid >> 5, lane = tid & 31;
    const int c0 = warp * 256 + lane * 8;
    const __half* M = slot ? g_Eyy : g_Exx;
    const float* wv = g_wsym[par][slot] + b * NN;

    __shared__ float swap_s[RBS];
    __shared__ float rowpart[RBS][9];

    const float4 w0 = *(const float4*)&wv[c0];
    const float4 w1 = *(const float4*)&wv[c0 + 4];

    #pragma unroll
    for (int s = 0; s < 2; s++) {
        const int i = s ? (NRB - 1 - bx) : bx;
        const int start = i * RBS;
        const bool wact = (warp * 256 + 256) > start;   // warp-uniform
        const bool lact = c0 >= start;                  // per-lane

        __syncthreads();
        if (tid < RBS) swap_s[tid] = wv[start + tid];
        __syncthreads();

        if (wact) {
            const __half* Srow = M + ((size_t)b * NN + start) * NN + c0;
            float colacc[8];
            #pragma unroll
            for (int j = 0; j < 8; j++) colacc[j] = 0.f;

            #pragma unroll
            for (int g8 = 0; g8 < RBS / 8; g8++) {
                uint4 m[8];
                #pragma unroll
                for (int rr = 0; rr < 8; rr++)
                    m[rr] = lact ? __ldg((const uint4*)(Srow + (size_t)(g8 * 8 + rr) * NN))
                                 : make_uint4(0u, 0u, 0u, 0u);

                float rd[8];
                rows8_fp16(m, &swap_s[g8 * 8], w0, w1, rd, colacc);

                #pragma unroll
                for (int o = 16; o; o >>= 1) {
                    #pragma unroll
                    for (int rr = 0; rr < 8; rr++)
                        rd[rr] += __shfl_xor_sync(0xffffffffu, rd[rr], o);
                }
                if (lane == 0) {
                    #pragma unroll
                    for (int rr = 0; rr < 8; rr++) rowpart[g8 * 8 + rr][warp] = rd[rr];
                }
            }

            if (lact) {
                float* cp = &g_colpartS[slot][i][b][c0];
                *(float4*)cp       = make_float4(colacc[0], colacc[1], colacc[2], colacc[3]);
                *(float4*)(cp + 4) = make_float4(colacc[4], colacc[5], colacc[6], colacc[7]);
            }
        } else if (lane == 0) {
            #pragma unroll
            for (int r = 0; r < RBS; r++) rowpart[r][warp] = 0.f;
        }

        __syncthreads();
        if (tid < RBS) {
            float tot = 0.f;
            #pragma unroll
            for (int w = 0; w < 8; w++) tot += rowpart[tid][w];
            g_symrow[slot][b * NN + start + tid] = tot;
        }
    }
}

// ---------------- sym finalize: S[r] = rowsum(r) + sum_{j<blk(r)} colpartS[j][r] ----------------
__global__ void sym_fin(const float* __restrict__ a, const float* __restrict__ bm,
                        int par, int mode)
{
    const int slot = blockIdx.y;
    const int i = blockIdx.x * 256 + threadIdx.x;       // i = b*NN + r
    const int b = i >> 11, r = i & (NN - 1);
    const int blk = r >> 4;                             // RBS = 16

    const float* cp = &g_colpartS[slot][0][b][r];
    const size_t stride = (size_t)BB * NN;
    float T0 = 0.f, T1 = 0.f, T2 = 0.f, T3 = 0.f;
    int j = 0;
    for (; j + 4 <= blk; j += 4) {
        T0 += cp[(size_t)j * stride];
        T1 += cp[(size_t)(j + 1) * stride];
        T2 += cp[(size_t)(j + 2) * stride];
        T3 += cp[(size_t)(j + 3) * stride];
    }
    for (; j < blk; j++) T0 += cp[(size_t)j * stride];
    float T = g_symrow[slot][i] + ((T0 + T1) + (T2 + T3));

    const float* meas = slot ? bm : a;
    if (mode == 0) {
        float pn = 0.5f * (g_pot[2 + slot][i] - logf(T));
        g_pot[2 + slot][i] = pn;
        g_wsym[par ^ 1][slot][i] = meas[i] * __expf(pn);
    } else {
        g_c[2 + slot][i] = -meas[i] * logf(T);
    }
}

// ---------------- final scalar ----------------
__global__ void final_reduce(float* __restrict__ out)
{
    const int tid = threadIdx.x;
    float s = 0.f;
    for (int i = tid; i < BB * NN; i += 1024)
        s += (g_c[0][i] + g_c[1][i]) - (g_c[2][i] + g_c[3][i]);
    #pragma unroll
    for (int o = 16; o; o >>= 1) s += __shfl_xor_sync(0xffffffffu, s, o);
    __shared__ float sm[32];
    if ((tid & 31) == 0) sm[tid >> 5] = s;
    __syncthreads();
    if (tid < 32) {
        float v = sm[tid];
        #pragma unroll
        for (int o = 16; o; o >>= 1) v += __shfl_xor_sync(0xffffffffu, v, o);
        if (tid == 0) out[0] = v / (float)BB;
    }
}

// ---------------- launcher: separate phase loops (L2 residency per phase) ----------------
extern "C" void kernel_launch(void* const* d_in, const int* in_sizes, int n_in,
                              void* d_out, int out_size)
{
    const float* x  = (const float*)d_in[0];
    const float* a  = (const float*)d_in[1];
    const float* y  = (const float*)d_in[2];
    const float* bm = (const float*)d_in[3];
    float* out = (float*)d_out;

    shift_kernel<<<dim3(16, BB), 128>>>(x, y);
    init_kernel<<<(BB * NN + 255) / 256, 256>>>(a, bm);

    dim3 bg(16, 16, BB);     // 128x128 tiles
    dim3 xg(XNRB, BB);
    dim3 smg(NRB / 2, BB, 2);
    dim3 sfg(BB * NN / 256, 2);

    // ---- xy phase ----
    build_xy<<<bg, 256>>>(x, y);
    for (int it = 0; it < 10; it++) {
        xy_main<<<xg, 256>>>(a, it & 1, 0);
        xy_fin<<<BB * NN / 256, 256>>>(bm, 0);
    }
    xy_main<<<xg, 256>>>(a, 0, 1);           // c0 + final colparts (wap parity 0)
    xy_fin<<<BB * NN / 256, 256>>>(bm, 1);   // c1

    // ---- merged symmetric phases (upper triangles only) ----
    build_xx<<<bg, 256>>>(x);
    build_yy<<<bg, 256>>>(y);
    for (int it = 0; it < 10; it++) {
        sym_main<<<smg, 256>>>(it & 1);
        sym_fin<<<sfg, 256>>>(a, bm, it & 1, 0);
    }
    sym_main<<<smg, 256>>>(0);               // final weights at parity 0
    sym_fin<<<sfg, 256>>>(a, bm, 0, 1);      // c2, c3

    final_reduce<<<1, 1024>>>(out);
}

// round 17
// speedup vs baseline: 1.1063x; 1.0418x over previous
#include <cuda_runtime.h>
#include <cuda_fp16.h>
#include <cuda_bf16.h>
#include <math.h>
#include <stdint.h>

#define BB 8
#define NN 2048
#define DD 32
#define XRBS 16                     // rows per xy row-block
#define XNRB (NN / XRBS)            // 128
#define RBS 16                      // rows per sym row-block
#define NRB (NN / RBS)              // 128

// ---------------- scratch (device globals; no allocations) ----------------
__device__ __nv_bfloat16 g_Exy[(size_t)BB * NN * NN]; // exp((sh_l - dist(x_l,y_k))/2), bf16
__device__ __half g_Exx[(size_t)BB * NN * NN];        // exp(-dist/2), fp16 (upper tiles valid)
__device__ __half g_Eyy[(size_t)BB * NN * NN];
__device__ float g_shift[BB * NN];
__device__ float g_pot[4][BB * NN];              // 0:f 1:g 2:fx 3:fy
__device__ float g_wg[BB * NN];                  // b * exp(g)
__device__ float g_wap[2][BB * NN];              // a * exp(f - sh/2), parity buffered
__device__ float g_wsym[2][2][BB * NN];          // [parity][0:xx,1:yy]
__device__ float g_colpart[XNRB][BB][NN];        // xy column partial sums
__device__ float g_colpartS[2][NRB][BB][NN];     // sym column partials per slot
__device__ float g_symrow[2][BB * NN];           // sym row sums (cols >= start part)
__device__ float g_c[4][BB * NN];                // eval contributions

// ---------------- small helpers ----------------
__device__ __forceinline__ uint32_t f2tf32(float f) {
    uint32_t r;
    asm("cvt.rna.tf32.f32 %0, %1;" : "=r"(r) : "f"(f));
    return r;
}
__device__ __forceinline__ void mma_tf32(float d[4],
    uint32_t a0, uint32_t a1, uint32_t a2, uint32_t a3, uint32_t b0, uint32_t b1)
{
    asm("mma.sync.aligned.m16n8k8.row.col.f32.tf32.tf32.f32 "
        "{%0,%1,%2,%3}, {%4,%5,%6,%7}, {%8,%9}, {%0,%1,%2,%3};"
        : "+f"(d[0]), "+f"(d[1]), "+f"(d[2]), "+f"(d[3])
        : "r"(a0), "r"(a1), "r"(a2), "r"(a3), "r"(b0), "r"(b1));
}

// ---------------- row shifts ----------------
__global__ void shift_kernel(const float* __restrict__ x, const float* __restrict__ y)
{
    const int b = blockIdx.y;
    const int l = blockIdx.x * 128 + threadIdx.x;
    const float* Pb = x + (size_t)b * NN * DD;
    const float* Qb = y + (size_t)b * NN * DD;

    __shared__ float sq[128][DD + 1];
    for (int i = threadIdx.x; i < 128 * DD; i += 128)
        sq[i >> 5][i & 31] = Qb[i];
    __syncthreads();

    float p[DD];
    #pragma unroll
    for (int d = 0; d < DD; d++) p[d] = Pb[(size_t)l * DD + d];

    float mn = 3.4e38f;
    for (int k = 0; k < 128; k++) {
        float acc = 0.f;
        #pragma unroll
        for (int d = 0; d < DD; d++) {
            float df = p[d] - sq[k][d];
            acc = fmaf(df, df, acc);
        }
        mn = fminf(mn, acc);
    }
    g_shift[b * NN + l] = mn;
}

// ---------------- init ----------------
__global__ void init_kernel(const float* __restrict__ a, const float* __restrict__ bm)
{
    int i = blockIdx.x * 256 + threadIdx.x;
    if (i < BB * NN) {
        g_pot[0][i] = 0.f; g_pot[1][i] = 0.f;
        g_pot[2][i] = 0.f; g_pot[3][i] = 0.f;
        g_wg[i] = bm[i];
        g_wap[0][i] = a[i] * __expf(-0.5f * g_shift[i]);
        g_wsym[0][0][i] = a[i];
        g_wsym[0][1][i] = bm[i];
    }
}

// ---------------- tensor-core build core (tf32 3-product split) ----------------
// block 256 (8 warps), tile 128x128, static smem, lb(256,3). (R13 form — fastest measured.)
template <int USE_SHIFT, int OUT>
__device__ __forceinline__ void build_core(const float* __restrict__ P,
                                           const float* __restrict__ Q,
                                           int b, int l0, int k0)
{
    __shared__ float sp[128][DD + 4];
    __shared__ float sq[128][DD + 4];
    __shared__ float snp[128], snq[128];

    const int tid = threadIdx.x;
    const float* Pb = P + (size_t)b * NN * DD;
    const float* Qb = Q + (size_t)b * NN * DD;

    for (int i = tid; i < 128 * DD; i += 256) {
        int r = i >> 5, d = i & 31;
        sp[r][d] = Pb[(size_t)(l0 + r) * DD + d];
        sq[r][d] = Qb[(size_t)(k0 + r) * DD + d];
    }
    __syncthreads();

    if (tid < 128) {
        float s = 0.f;
        #pragma unroll
        for (int d = 0; d < DD; d++) s = fmaf(sp[tid][d], sp[tid][d], s);
        snp[tid] = s;
    } else {
        int r = tid - 128;
        float s = 0.f;
        #pragma unroll
        for (int d = 0; d < DD; d++) s = fmaf(sq[r][d], sq[r][d], s);
        snq[r] = s;
    }
    __syncthreads();

    const int warp = tid >> 5, lane = tid & 31;
    const int g = lane >> 2, tg = lane & 3;
    const int nb = warp * 16;

    float acc[8][2][4];
    #pragma unroll
    for (int r = 0; r < 8; r++)
        #pragma unroll
        for (int c = 0; c < 2; c++)
            #pragma unroll
            for (int q = 0; q < 4; q++) acc[r][c][q] = 0.f;

    #pragma unroll
    for (int kt = 0; kt < 4; kt++) {
        const int kc = kt * 8;
        uint32_t bh[2][2], bl[2][2];
        #pragma unroll
        for (int c = 0; c < 2; c++) {
            float f0 = sq[nb + c * 8 + g][kc + tg];
            float f1 = sq[nb + c * 8 + g][kc + tg + 4];
            bh[c][0] = f2tf32(f0); bl[c][0] = f2tf32(f0 - __uint_as_float(bh[c][0]));
            bh[c][1] = f2tf32(f1); bl[c][1] = f2tf32(f1 - __uint_as_float(bh[c][1]));
        }
        #pragma unroll
        for (int r = 0; r < 8; r++) {
            float a00 = sp[r * 16 + g][kc + tg];
            float a10 = sp[r * 16 + g + 8][kc + tg];
            float a01 = sp[r * 16 + g][kc + tg + 4];
            float a11 = sp[r * 16 + g + 8][kc + tg + 4];
            uint32_t h0 = f2tf32(a00), h1 = f2tf32(a10), h2 = f2tf32(a01), h3 = f2tf32(a11);
            uint32_t l0r = f2tf32(a00 - __uint_as_float(h0));
            uint32_t l1r = f2tf32(a10 - __uint_as_float(h1));
            uint32_t l2r = f2tf32(a01 - __uint_as_float(h2));
            uint32_t l3r = f2tf32(a11 - __uint_as_float(h3));
            #pragma unroll
            for (int c = 0; c < 2; c++) {
                mma_tf32(acc[r][c], h0, h1, h2, h3, bh[c][0], bh[c][1]);
                mma_tf32(acc[r][c], h0, h1, h2, h3, bl[c][0], bl[c][1]);
                mma_tf32(acc[r][c], l0r, l1r, l2r, l3r, bh[c][0], bh[c][1]);
            }
        }
    }

    const size_t base = (size_t)b * NN * NN;
    #pragma unroll
    for (int r = 0; r < 8; r++) {
        const int row0 = l0 + r * 16 + g;
        const int row1 = row0 + 8;
        const float nx0 = snp[r * 16 + g], nx1 = snp[r * 16 + g + 8];
        const float sh0 = USE_SHIFT ? g_shift[b * NN + row0] : 0.f;
        const float sh1 = USE_SHIFT ? g_shift[b * NN + row1] : 0.f;
        #pragma unroll
        for (int c = 0; c < 2; c++) {
            const int col = k0 + nb + c * 8 + tg * 2;
            const float ny0 = snq[nb + c * 8 + tg * 2];
            const float ny1 = snq[nb + c * 8 + tg * 2 + 1];
            float e00 = __expf(0.5f * (sh0 - fmaxf(nx0 + ny0 - 2.f * acc[r][c][0], 0.f)));
            float e01 = __expf(0.5f * (sh0 - fmaxf(nx0 + ny1 - 2.f * acc[r][c][1], 0.f)));
            float e10 = __expf(0.5f * (sh1 - fmaxf(nx1 + ny0 - 2.f * acc[r][c][2], 0.f)));
            float e11 = __expf(0.5f * (sh1 - fmaxf(nx1 + ny1 - 2.f * acc[r][c][3], 0.f)));
            if (OUT == 0) {
                *(__nv_bfloat162*)&g_Exy[base + (size_t)row0 * NN + col] =
                    __floats2bfloat162_rn(e00, e01);
                *(__nv_bfloat162*)&g_Exy[base + (size_t)row1 * NN + col] =
                    __floats2bfloat162_rn(e10, e11);
            } else {
                __half* M = (OUT == 1) ? g_Exx : g_Eyy;
                *(__half2*)&M[base + (size_t)row0 * NN + col] = __floats2half2_rn(e00, e01);
                *(__half2*)&M[base + (size_t)row1 * NN + col] = __floats2half2_rn(e10, e11);
            }
        }
    }
}

__global__ void __launch_bounds__(256, 3) build_xy(const float* __restrict__ x,
                                                   const float* __restrict__ y)
{ build_core<1, 0>(x, y, blockIdx.z, blockIdx.y * 128, blockIdx.x * 128); }

// Merged sym builds: grid z = slot*BB + b. Upper-staircase tiles only.
__global__ void __launch_bounds__(256, 3) build_sym(const float* __restrict__ x,
                                                    const float* __restrict__ y)
{
    if (blockIdx.x < blockIdx.y) return;
    const int slot = blockIdx.z / BB;
    const int b = blockIdx.z % BB;
    if (slot == 0) build_core<0, 1>(x, x, b, blockIdx.y * 128, blockIdx.x * 128);
    else           build_core<0, 2>(y, y, b, blockIdx.y * 128, blockIdx.x * 128);
}

// ---------------- row-batch compute helpers (8 rows) ----------------
__device__ __forceinline__ void rows8_bf16(const uint4 m[8], const float* swap8,
                                           const float4& wg0, const float4& wg1,
                                           float rd[8], float colacc[8])
{
    #pragma unroll
    for (int rr = 0; rr < 8; rr++) {
        float2 e0 = __bfloat1622float2(*reinterpret_cast<const __nv_bfloat162*>(&m[rr].x));
        float2 e1 = __bfloat1622float2(*reinterpret_cast<const __nv_bfloat162*>(&m[rr].y));
        float2 e2 = __bfloat1622float2(*reinterpret_cast<const __nv_bfloat162*>(&m[rr].z));
        float2 e3 = __bfloat1622float2(*reinterpret_cast<const __nv_bfloat162*>(&m[rr].w));
        float wr = swap8[rr];
        float s = 0.f;
        s = fmaf(e0.x, wg0.x, s); s = fmaf(e0.y, wg0.y, s);
        s = fmaf(e1.x, wg0.z, s); s = fmaf(e1.y, wg0.w, s);
        s = fmaf(e2.x, wg1.x, s); s = fmaf(e2.y, wg1.y, s);
        s = fmaf(e3.x, wg1.z, s); s = fmaf(e3.y, wg1.w, s);
        rd[rr] = s;
        colacc[0] = fmaf(e0.x, wr, colacc[0]); colacc[1] = fmaf(e0.y, wr, colacc[1]);
        colacc[2] = fmaf(e1.x, wr, colacc[2]); colacc[3] = fmaf(e1.y, wr, colacc[3]);
        colacc[4] = fmaf(e2.x, wr, colacc[4]); colacc[5] = fmaf(e2.y, wr, colacc[5]);
        colacc[6] = fmaf(e3.x, wr, colacc[6]); colacc[7] = fmaf(e3.y, wr, colacc[7]);
    }
}

__device__ __forceinline__ void rows8_fp16(const uint4 m[8], const float* swap8,
                                           const float4& wg0, const float4& wg1,
                                           float rd[8], float colacc[8])
{
    #pragma unroll
    for (int rr = 0; rr < 8; rr++) {
        float2 e0 = __half22float2(*reinterpret_cast<const __half2*>(&m[rr].x));
        float2 e1 = __half22float2(*reinterpret_cast<const __half2*>(&m[rr].y));
        float2 e2 = __half22float2(*reinterpret_cast<const __half2*>(&m[rr].z));
        float2 e3 = __half22float2(*reinterpret_cast<const __half2*>(&m[rr].w));
        float wr = swap8[rr];
        float s = 0.f;
        s = fmaf(e0.x, wg0.x, s); s = fmaf(e0.y, wg0.y, s);
        s = fmaf(e1.x, wg0.z, s); s = fmaf(e1.y, wg0.w, s);
        s = fmaf(e2.x, wg1.x, s); s = fmaf(e2.y, wg1.y, s);
        s = fmaf(e3.x, wg1.z, s); s = fmaf(e3.y, wg1.w, s);
        rd[rr] = s;
        colacc[0] = fmaf(e0.x, wr, colacc[0]); colacc[1] = fmaf(e0.y, wr, colacc[1]);
        colacc[2] = fmaf(e1.x, wr, colacc[2]); colacc[3] = fmaf(e1.y, wr, colacc[3]);
        colacc[4] = fmaf(e2.x, wr, colacc[4]); colacc[5] = fmaf(e2.y, wr, colacc[5]);
        colacc[6] = fmaf(e3.x, wr, colacc[6]); colacc[7] = fmaf(e3.y, wr, colacc[7]);
    }
}

// ---------------- xy main pass: row sums + column partials, 8-deep MLP ----------------
// grid (XNRB=128, BB), block 256 = 8 warps; no reg cap (64 regs, m[8] batch intact)
__global__ void __launch_bounds__(256) xy_main(const float* __restrict__ a, int par, int mode)
{
    const int b = blockIdx.y, rb = blockIdx.x;
    const int tid = threadIdx.x, warp = tid >> 5, lane = tid & 31;
    const int c0 = warp * 256 + lane * 8;

    __shared__ float swap_s[XRBS];
    __shared__ float rowpart[XRBS][9];

    if (tid < XRBS) swap_s[tid] = g_wap[par][b * NN + rb * XRBS + tid];

    const float4 wg0 = *(const float4*)&g_wg[b * NN + c0];
    const float4 wg1 = *(const float4*)&g_wg[b * NN + c0 + 4];
    __syncthreads();

    const __nv_bfloat16* Srow = g_Exy + ((size_t)b * NN + rb * XRBS) * NN + c0;

    float colacc[8];
    #pragma unroll
    for (int j = 0; j < 8; j++) colacc[j] = 0.f;

    #pragma unroll
    for (int g8 = 0; g8 < XRBS / 8; g8++) {
        uint4 m[8];
        #pragma unroll
        for (int rr = 0; rr < 8; rr++)
            m[rr] = __ldg((const uint4*)(Srow + (size_t)(g8 * 8 + rr) * NN));

        float rd[8];
        rows8_bf16(m, &swap_s[g8 * 8], wg0, wg1, rd, colacc);

        #pragma unroll
        for (int o = 16; o; o >>= 1) {
            #pragma unroll
            for (int rr = 0; rr < 8; rr++)
                rd[rr] += __shfl_xor_sync(0xffffffffu, rd[rr], o);
        }
        if (lane == 0) {
            #pragma unroll
            for (int rr = 0; rr < 8; rr++) rowpart[g8 * 8 + rr][warp] = rd[rr];
        }
    }

    float* cp = &g_colpart[rb][b][c0];
    *(float4*)cp       = make_float4(colacc[0], colacc[1], colacc[2], colacc[3]);
    *(float4*)(cp + 4) = make_float4(colacc[4], colacc[5], colacc[6], colacc[7]);

    __syncthreads();

    if (tid < XRBS) {
        const int row = rb * XRBS + tid;
        const int idx = b * NN + row;
        float tot = 0.f;
        #pragma unroll
        for (int w = 0; w < 8; w++) tot += rowpart[tid][w];
        const float sh = g_shift[idx];
        if (mode == 0) {
            float fn = 0.5f * (g_pot[0][idx] - logf(tot) + 0.5f * sh);
            g_pot[0][idx] = fn;
            g_wap[par ^ 1][idx] = a[idx] * __expf(fn - 0.5f * sh);
        } else {
            g_c[0][idx] = a[idx] * (0.5f * sh - logf(tot));
        }
    }
}

// ---------------- xy finalize ----------------
__global__ void xy_fin(const float* __restrict__ bm, int mode)
{
    const int i = blockIdx.x * 256 + threadIdx.x;       // i = b*NN + k
    const int b = i >> 11, k = i & (NN - 1);
    float T = 0.f;
    #pragma unroll 8
    for (int rb = 0; rb < XNRB; rb++) T += g_colpart[rb][b][k];
    if (mode == 0) {
        float gn = 0.5f * (g_pot[1][i] - logf(T));
        g_pot[1][i] = gn;
        g_wg[i] = bm[i] * __expf(gn);
    } else {
        g_c[1][i] = -bm[i] * logf(T);
    }
}

// ---------------- sym main pass (SYMV, upper triangle) ----------------
// grid (NRB/2, BB, 2). Block bx handles row-blocks {bx, NRB-1-bx}, cols >= 16*i each.
__global__ void __launch_bounds__(256) sym_main(int par)
{
    const int slot = blockIdx.z, b = blockIdx.y, bx = blockIdx.x;
    const int tid = threadIdx.x, warp = tid >> 5, lane = tid & 31;
    const int c0 = warp * 256 + lane * 8;
    const __half* M = slot ? g_Eyy : g_Exx;
    const float* wv = g_wsym[par][slot] + b * NN;

    __shared__ float swap_s[RBS];
    __shared__ float rowpart[RBS][9];

    const float4 w0 = *(const float4*)&wv[c0];
    const float4 w1 = *(const float4*)&wv[c0 + 4];

    #pragma unroll
    for (int s = 0; s < 2; s++) {
        const int i = s ? (NRB - 1 - bx) : bx;
        const int start = i * RBS;
        const bool wact = (warp * 256 + 256) > start;   // warp-uniform
        const bool lact = c0 >= start;                  // per-lane

        __syncthreads();
        if (tid < RBS) swap_s[tid] = wv[start + tid];
        __syncthreads();

        if (wact) {
            const __half* Srow = M + ((size_t)b * NN + start) * NN + c0;
            float colacc[8];
            #pragma unroll
            for (int j = 0; j < 8; j++) colacc[j] = 0.f;

            #pragma unroll
            for (int g8 = 0; g8 < RBS / 8; g8++) {
                uint4 m[8];
                #pragma unroll
                for (int rr = 0; rr < 8; rr++)
                    m[rr] = lact ? __ldg((const uint4*)(Srow + (size_t)(g8 * 8 + rr) * NN))
                                 : make_uint4(0u, 0u, 0u, 0u);

                float rd[8];
                rows8_fp16(m, &swap_s[g8 * 8], w0, w1, rd, colacc);

                #pragma unroll
                for (int o = 16; o; o >>= 1) {
                    #pragma unroll
                    for (int rr = 0; rr < 8; rr++)
                        rd[rr] += __shfl_xor_sync(0xffffffffu, rd[rr], o);
                }
                if (lane == 0) {
                    #pragma unroll
                    for (int rr = 0; rr < 8; rr++) rowpart[g8 * 8 + rr][warp] = rd[rr];
                }
            }

            if (lact) {
                float* cp = &g_colpartS[slot][i][b][c0];
                *(float4*)cp       = make_float4(colacc[0], colacc[1], colacc[2], colacc[3]);
                *(float4*)(cp + 4) = make_float4(colacc[4], colacc[5], colacc[6], colacc[7]);
            }
        } else if (lane == 0) {
            #pragma unroll
            for (int r = 0; r < RBS; r++) rowpart[r][warp] = 0.f;
        }

        __syncthreads();
        if (tid < RBS) {
            float tot = 0.f;
            #pragma unroll
            for (int w = 0; w < 8; w++) tot += rowpart[tid][w];
            g_symrow[slot][b * NN + start + tid] = tot;
        }
    }
}

// ---------------- sym finalize: S[r] = rowsum(r) + sum_{j<blk(r)} colpartS[j][r] ----------------
__global__ void sym_fin(const float* __restrict__ a, const float* __restrict__ bm,
                        int par, int mode)
{
    const int slot = blockIdx.y;
    const int i = blockIdx.x * 256 + threadIdx.x;       // i = b*NN + r
    const int b = i >> 11, r = i & (NN - 1);
    const int blk = r >> 4;                             // RBS = 16

    const float* cp = &g_colpartS[slot][0][b][r];
    const size_t stride = (size_t)BB * NN;
    float T0 = 0.f, T1 = 0.f, T2 = 0.f, T3 = 0.f;
    int j = 0;
    for (; j + 4 <= blk; j += 4) {
        T0 += cp[(size_t)j * stride];
        T1 += cp[(size_t)(j + 1) * stride];
        T2 += cp[(size_t)(j + 2) * stride];
        T3 += cp[(size_t)(j + 3) * stride];
    }
    for (; j < blk; j++) T0 += cp[(size_t)j * stride];
    float T = g_symrow[slot][i] + ((T0 + T1) + (T2 + T3));

    const float* meas = slot ? bm : a;
    if (mode == 0) {
        float pn = 0.5f * (g_pot[2 + slot][i] - logf(T));
        g_pot[2 + slot][i] = pn;
        g_wsym[par ^ 1][slot][i] = meas[i] * __expf(pn);
    } else {
        g_c[2 + slot][i] = -meas[i] * logf(T);
    }
}

// ---------------- final scalar ----------------
__global__ void final_reduce(float* __restrict__ out)
{
    const int tid = threadIdx.x;
    float s = 0.f;
    for (int i = tid; i < BB * NN; i += 1024)
        s += (g_c[0][i] + g_c[1][i]) - (g_c[2][i] + g_c[3][i]);
    #pragma unroll
    for (int o = 16; o; o >>= 1) s += __shfl_xor_sync(0xffffffffu, s, o);
    __shared__ float sm[32];
    if ((tid & 31) == 0) sm[tid >> 5] = s;
    __syncthreads();
    if (tid < 32) {
        float v = sm[tid];
        #pragma unroll
        for (int o = 16; o; o >>= 1) v += __shfl_xor_sync(0xffffffffu, v, o);
        if (tid == 0) out[0] = v / (float)BB;
    }
}

// ---------------- launcher: separate phase loops (L2 residency per phase) ----------------
extern "C" void kernel_launch(void* const* d_in, const int* in_sizes, int n_in,
                              void* d_out, int out_size)
{
    const float* x  = (const float*)d_in[0];
    const float* a  = (const float*)d_in[1];
    const float* y  = (const float*)d_in[2];
    const float* bm = (const float*)d_in[3];
    float* out = (float*)d_out;

    shift_kernel<<<dim3(16, BB), 128>>>(x, y);
    init_kernel<<<(BB * NN + 255) / 256, 256>>>(a, bm);

    dim3 bg(16, 16, BB);         // xy build: 128x128 tiles
    dim3 bgs(16, 16, BB * 2);    // merged sym builds (z = slot*BB + b)
    dim3 xg(XNRB, BB);
    dim3 smg(NRB / 2, BB, 2);
    dim3 sfg(BB * NN / 256, 2);

    // ---- xy phase ----
    build_xy<<<bg, 256>>>(x, y);
    for (int it = 0; it < 10; it++) {
        xy_main<<<xg, 256>>>(a, it & 1, 0);
        xy_fin<<<BB * NN / 256, 256>>>(bm, 0);
    }
    xy_main<<<xg, 256>>>(a, 0, 1);           // c0 + final colparts (wap parity 0)
    xy_fin<<<BB * NN / 256, 256>>>(bm, 1);   // c1

    // ---- merged symmetric phases (upper triangles only) ----
    build_sym<<<bgs, 256>>>(x, y);
    for (int it = 0; it < 10; it++) {
        sym_main<<<smg, 256>>>(it & 1);
        sym_fin<<<sfg, 256>>>(a, bm, it & 1, 0);
    }
    sym_main<<<smg, 256>>>(0);               // final weights at parity 0
    sym_fin<<<sfg, 256>>>(a, bm, 0, 1);      // c2, c3

    final_reduce<<<1, 1024>>>(out);
}